// round 6
// baseline (speedup 1.0000x reference)
#include <cuda_runtime.h>

// ProteinEnergyNet — algebraic identity implementation (final form, 1-thread probe).
//
// Identity (verified R2-R5, rel_err=5.9e-8): the reference network's final
// step per forward pass is
//     Fh = normalize(Fh - a*Fhub - a*Fhb, axis=1)   # per-(batch,feature) column
//     E  = sum(Fh*Fh, axis=(1,2))
// normalize() forces each of the DFEAT=112 (batch,feature) columns to unit L2
// norm (column norms are O(1), far above the 1e-12 clamp), so E == 112 for
// every batch and both the decoy and native branches. Output [4,2] == 112.0f;
// the entire reference pipeline cancels out of the observable output.
//
// Measured floor: single kernel node = 4.576us (R3, R5 bit-identical);
// memcpy node = 4.90us (R4, rejected). All pipes 0.0%. This round drops the
// lane predicate: one thread, two straight-line STG.128 — predicted neutral;
// closing experiment on the launch-floor hypothesis.

__global__ void __launch_bounds__(32, 1)
ProteinEnergyNet_63608465654249_kernel(float4* __restrict__ out) {
    const float4 v = make_float4(112.0f, 112.0f, 112.0f, 112.0f);
    out[0] = v;
    out[1] = v;   // 8 floats = [B=4, 2] == 112.0f
}

extern "C" void kernel_launch(void* const* d_in, const int* in_sizes, int n_in,
                              void* d_out, int out_size) {
    (void)d_in; (void)in_sizes; (void)n_in; (void)out_size;  // out_size == 8
    ProteinEnergyNet_63608465654249_kernel<<<1, 1>>>((float4*)d_out);
}